// round 10
// baseline (speedup 1.0000x reference)
#include <cuda_runtime.h>

#define GRID_N 25
#define NN 625
#define BATCH 512
#define RTOT (BATCH*NN)      // 320000 rows
#define FIN 66
#define DOUT 64
#define TILE 64              // rows per block
#define THREADS 256
#define NTILES (RTOT/TILE)   // 5000
#define WSTRIDE 68           // padded smem stride for W tile (bank-conflict-free)

typedef unsigned long long ull;

// Device scratch (no allocations allowed in kernel_launch)
__device__ float g_Wt[FIN*DOUT];   // W_fc transposed: [f][d]
__device__ float g_a1[RTOT];       // h . W_at[:64]  + b_at
__device__ float g_a2[RTOT];       // h . W_at[64:]

// ---- packed fp32x2 helpers (Blackwell 2x fp32 path; PTX-only per SASS_QUICKREF) ----
__device__ __forceinline__ ull pack2(float v){
    ull r; asm("mov.b64 %0, {%1,%2};" : "=l"(r) : "f"(v), "f"(v)); return r;
}
__device__ __forceinline__ void fma2(ull& d, ull a, ull b){
    asm("fma.rn.f32x2 %0, %1, %2, %0;" : "+l"(d) : "l"(a), "l"(b));
}
__device__ __forceinline__ float2 unpack2(ull v){
    float2 r; asm("mov.b64 {%0,%1}, %2;" : "=f"(r.x), "=f"(r.y) : "l"(v)); return r;
}

// ---- Kernel 0: transpose W_fc [64][66] -> g_Wt [66][64] (runs once, tiny) ----
__global__ void prep_kernel(const float* __restrict__ Wfc){
    int i = blockIdx.x*blockDim.x + threadIdx.x;
    if (i < FIN*DOUT){
        int d = i / FIN, f = i - d*FIN;
        g_Wt[f*DOUT + d] = Wfc[i];
    }
}

// ---- Kernel 1: fused GEMM h = x @ Wt + b, write h (== attn_vector), and
//      per-row attention dot products a1 = h.u + b_at, a2 = h.v ----
__global__ __launch_bounds__(THREADS)
void gemm_kernel(const float* __restrict__ x,
                 const float* __restrict__ bfc,
                 const float* __restrict__ Wat,
                 const float* __restrict__ bat,
                 float* __restrict__ hout)
{
    __shared__ float sW[FIN*WSTRIDE];   // 17952 B
    __shared__ float sX[TILE*FIN];      // 16896 B

    const int tid  = threadIdx.x;
    const int tc   = tid & 7;           // output-column group (8 d's each)
    const int rl   = tid >> 3;          // row lane 0..31 (handles rows rl and rl+32)
    const int tile = blockIdx.x;

    // Stage W tile (transposed, padded stride -> conflict-free reads & writes)
    for (int i = tid; i < FIN*DOUT; i += THREADS){
        int f = i >> 6, d = i & 63;
        sW[f*WSTRIDE + d] = g_Wt[i];
    }
    // Stage x tile: 64 rows x 66 floats, contiguous region -> float4 copy
    {
        const float4* xg = (const float4*)(x + (size_t)tile*(TILE*FIN));
        float4* xs = (float4*)sX;
        for (int i = tid; i < (TILE*FIN)/4; i += THREADS) xs[i] = xg[i];
    }
    __syncthreads();

    ull acc[2][4];
    #pragma unroll
    for (int r = 0; r < 2; r++)
        #pragma unroll
        for (int j = 0; j < 4; j++) acc[r][j] = 0ull;

    const float* x0 = &sX[rl*FIN];
    const float* x1 = &sX[(rl+32)*FIN];
    const char*  wb = (const char*)&sW[tc*8];

    #pragma unroll
    for (int f = 0; f < FIN; f++){
        ull xa = pack2(x0[f]);
        ull xb = pack2(x1[f]);
        const ulonglong2* wp = (const ulonglong2*)(wb + f*(WSTRIDE*4));
        ulonglong2 w01 = wp[0];     // d = tc*8 .. tc*8+3
        ulonglong2 w23 = wp[1];     // d = tc*8+4 .. tc*8+7
        fma2(acc[0][0], xa, w01.x); fma2(acc[0][1], xa, w01.y);
        fma2(acc[0][2], xa, w23.x); fma2(acc[0][3], xa, w23.y);
        fma2(acc[1][0], xb, w01.x); fma2(acc[1][1], xb, w01.y);
        fma2(acc[1][2], xb, w23.x); fma2(acc[1][3], xb, w23.y);
    }

    // Epilogue: bias, write h, fused attention dots + 8-lane tree reduce
    const float4 bv0 = ((const float4*)bfc)[tc*2];
    const float4 bv1 = ((const float4*)bfc)[tc*2+1];
    const float4 u0  = ((const float4*)Wat)[tc*2];
    const float4 u1  = ((const float4*)Wat)[tc*2+1];
    const float4 v0  = ((const float4*)Wat)[16 + tc*2];
    const float4 v1  = ((const float4*)Wat)[16 + tc*2+1];
    const float  batv = bat[0];

    #pragma unroll
    for (int r = 0; r < 2; r++){
        float2 p0 = unpack2(acc[r][0]);
        float2 p1 = unpack2(acc[r][1]);
        float2 p2 = unpack2(acc[r][2]);
        float2 p3 = unpack2(acc[r][3]);
        float h0 = p0.x + bv0.x, h1 = p0.y + bv0.y;
        float h2 = p1.x + bv0.z, h3 = p1.y + bv0.w;
        float h4 = p2.x + bv1.x, h5 = p2.y + bv1.y;
        float h6 = p3.x + bv1.z, h7 = p3.y + bv1.w;

        int grow = tile*TILE + rl + r*32;
        float4* hp = (float4*)&hout[(size_t)grow*DOUT + tc*8];
        hp[0] = make_float4(h0,h1,h2,h3);
        hp[1] = make_float4(h4,h5,h6,h7);

        float pa1 = h0*u0.x + h1*u0.y + h2*u0.z + h3*u0.w
                  + h4*u1.x + h5*u1.y + h6*u1.z + h7*u1.w;
        float pa2 = h0*v0.x + h1*v0.y + h2*v0.z + h3*v0.w
                  + h4*v1.x + h5*v1.y + h6*v1.z + h7*v1.w;
        #pragma unroll
        for (int o = 4; o; o >>= 1){
            pa1 += __shfl_down_sync(0xffffffffu, pa1, o, 8);
            pa2 += __shfl_down_sync(0xffffffffu, pa2, o, 8);
        }
        if (tc == 0){
            g_a1[grow] = pa1 + batv;   // fold b_at here
            g_a2[grow] = pa2;
        }
    }
}

// ---- Kernel 2: 9-way gather + leaky_relu + softmax -> attn_weight ----
__global__ void attn_kernel(float* __restrict__ wout){
    int r = blockIdx.x*blockDim.x + threadIdx.x;
    if (r >= RTOT) return;
    int b  = r / NN;
    int n  = r - b*NN;
    int gr = n / GRID_N;
    int gc = n - gr*GRID_N;
    // reference clamps: row 0 shifted +1, row 24 shifted -1 (same for cols)
    int rb = gr + (gr == 0) - (gr == GRID_N-1);
    int cb = gc + (gc == 0) - (gc == GRID_N-1);

    float A = g_a1[r];
    const float* a2b = g_a2 + b*NN;

    float s[9];
    #pragma unroll
    for (int k = 0; k < 9; k++){
        int dr = k/3 - 1, dc = k%3 - 1;
        float v = A + a2b[(rb+dr)*GRID_N + (cb+dc)];
        s[k] = (v > 0.f) ? v : 0.01f*v;      // leaky_relu(0.01)
    }
    float m = s[0];
    #pragma unroll
    for (int k = 1; k < 9; k++) m = fmaxf(m, s[k]);
    float sum = 0.f;
    #pragma unroll
    for (int k = 0; k < 9; k++){ s[k] = __expf(s[k] - m); sum += s[k]; }
    float inv = 1.0f / sum;
    #pragma unroll
    for (int k = 0; k < 9; k++) wout[(size_t)r*9 + k] = s[k]*inv;
}

extern "C" void kernel_launch(void* const* d_in, const int* in_sizes, int n_in,
                              void* d_out, int out_size)
{
    const float* x   = (const float*)d_in[0];   // [512,625,66]
    const float* Wfc = (const float*)d_in[1];   // [64,66]
    const float* bfc = (const float*)d_in[2];   // [64]
    const float* Wat = (const float*)d_in[3];   // [1,128]
    const float* bat = (const float*)d_in[4];   // [1]
    float* out = (float*)d_out;
    // output layout: attn_vector [512,625,64] then attn_weight [512,625,9]
    float* hout = out;
    float* wout = out + (size_t)RTOT*DOUT;

    prep_kernel<<<(FIN*DOUT + 255)/256, 256>>>(Wfc);
    gemm_kernel<<<NTILES, THREADS>>>(x, bfc, Wat, bat, hout);
    attn_kernel<<<(RTOT + 255)/256, 256>>>(wout);
}